// round 2
// baseline (speedup 1.0000x reference)
#include <cuda_runtime.h>

#define IC 1152
#define OC 10
#define ID 8
#define OD 16
#define BATCH 32
#define NI 8
#define NBLK (IC / NI)     // 144
#define THREADS 320        // 10 warps: warp = oc, lane = batch

typedef unsigned long long ull;

__device__ __forceinline__ ull ffma2(ull a, ull b, ull c) {
    ull d; asm("fma.rn.f32x2 %0, %1, %2, %3;" : "=l"(d) : "l"(a), "l"(b), "l"(c)); return d;
}
__device__ __forceinline__ ull fmul2(ull a, ull b) {
    ull d; asm("mul.rn.f32x2 %0, %1, %2;" : "=l"(d) : "l"(a), "l"(b)); return d;
}
__device__ __forceinline__ ull fadd2(ull a, ull b) {
    ull d; asm("add.rn.f32x2 %0, %1, %2;" : "=l"(d) : "l"(a), "l"(b)); return d;
}
__device__ __forceinline__ ull pack2(float x, float y) {
    ull u; asm("mov.b64 %0, {%1, %2};" : "=l"(u) : "f"(x), "f"(y)); return u;
}
__device__ __forceinline__ void unpack2(ull u, float& x, float& y) {
    asm("mov.b64 {%0, %1}, %2;" : "=f"(x), "=f"(y) : "l"(u));
}
__device__ __forceinline__ float frcp(float x) {
    float y; asm("rcp.approx.f32 %0, %1;" : "=f"(y) : "f"(x)); return y;
}

__global__ void caps_zero_kernel(float* out) {
    int i = blockIdx.x * blockDim.x + threadIdx.x;
    if (i < BATCH * OC * OD) out[i] = 0.0f;
}

__global__ __launch_bounds__(THREADS, 1) void caps_kernel(
    const float* __restrict__ x, const float* __restrict__ w, float* __restrict__ out)
{
    __shared__ __align__(16) float ws_sm[OC * ID * OD];  // normalized weights, 1280 f
    __shared__ float wsum_sm[OC * ID];                   // per-(c,d) row sums, 80 f
    __shared__ float xn_sm[ID][BATCH];                   // normalized x, [d][b]
    __shared__ float alpha_sm[OC * BATCH];

    const int t    = threadIdx.x;
    const int lane = t & 31;   // batch index
    const int c    = t >> 5;   // output capsule (warp id)
    const int i0   = blockIdx.x * NI;

    // ---- prefetch first i ----
    float4 wv = *(const float4*)(w + (size_t)i0 * (OC * ID * OD) + t * 4);
    float4 xv = make_float4(0.f, 0.f, 0.f, 0.f);
    if (t < 2 * BATCH) {
        int b = t >> 1, half = t & 1;
        xv = *(const float4*)(x + ((size_t)b * IC + i0) * ID + half * 4);
    }

    ull acc[8];
    #pragma unroll
    for (int j = 0; j < 8; j++) acc[j] = pack2(0.f, 0.f);

    #pragma unroll 1
    for (int ii = 0; ii < NI; ii++) {
        // ---- stage weights: normalize each (c,d) row over od, store ŵ + wsum ----
        {
            float ps  = wv.x + wv.y + wv.z + wv.w;
            float tot = ps + __shfl_xor_sync(0xffffffffu, ps, 1);
            tot += __shfl_xor_sync(0xffffffffu, tot, 2);
            float r = frcp(tot);
            float4 wn; wn.x = wv.x * r; wn.y = wv.y * r; wn.z = wv.z * r; wn.w = wv.w * r;
            *(float4*)(ws_sm + t * 4) = wn;
            if ((t & 3) == 0) wsum_sm[t >> 2] = tot;
        }
        // ---- stage x: normalize over id, transpose to [d][b] ----
        if (t < 2 * BATCH) {
            int b = t >> 1, half = t & 1;
            float ps  = xv.x + xv.y + xv.z + xv.w;
            float tot = ps + __shfl_xor_sync(0xffffffffu, ps, 1);
            float r = frcp(tot);
            xn_sm[half * 4 + 0][b] = xv.x * r;
            xn_sm[half * 4 + 1][b] = xv.y * r;
            xn_sm[half * 4 + 2][b] = xv.z * r;
            xn_sm[half * 4 + 3][b] = xv.w * r;
        }
        __syncthreads();

        // ---- prefetch next i while computing this one ----
        if (ii + 1 < NI) {
            wv = *(const float4*)(w + (size_t)(i0 + ii + 1) * (OC * ID * OD) + t * 4);
            if (t < 2 * BATCH) {
                int b = t >> 1, half = t & 1;
                xv = *(const float4*)(x + ((size_t)b * IC + (i0 + ii + 1)) * ID + half * 4);
            }
        }

        const float* wc = ws_sm + c * (ID * OD);
        float xn[8];
        #pragma unroll
        for (int d = 0; d < 8; d++) xn[d] = xn_sm[d][lane];

        // ---- iteration 1 (h0 uniform ⇒ h1[o] = Σ_d xn[d]·ŵ[d,o]) ----
        ull h[8];
        #pragma unroll
        for (int j = 0; j < 8; j++) h[j] = pack2(0.f, 0.f);
        #pragma unroll
        for (int d = 0; d < 8; d++) {
            ull xp = pack2(xn[d], xn[d]);
            const ulonglong2* wr = (const ulonglong2*)(wc + d * 16);
            #pragma unroll
            for (int k = 0; k < 4; k++) {
                ulonglong2 wk = wr[k];
                h[2 * k]     = ffma2(xp, wk.x, h[2 * k]);
                h[2 * k + 1] = ffma2(xp, wk.y, h[2 * k + 1]);
            }
        }

        // ---- iterations 2..5 (scale-invariant ⇒ no per-iter normalization) ----
        #pragma unroll 1
        for (int it = 0; it < 4; it++) {
            float den[8];
            #pragma unroll
            for (int d = 0; d < 8; d++) {
                const ulonglong2* wr = (const ulonglong2*)(wc + d * 16);
                ull p = pack2(0.f, 0.f);
                #pragma unroll
                for (int k = 0; k < 4; k++) {
                    ulonglong2 wk = wr[k];
                    p = ffma2(h[2 * k],     wk.x, p);
                    p = ffma2(h[2 * k + 1], wk.y, p);
                }
                float pa, pb; unpack2(p, pa, pb);
                den[d] = pa + pb;
            }
            ull xrp[8];
            #pragma unroll
            for (int d = 0; d < 8; d++) {
                float xr = xn[d] * frcp(den[d]);
                xrp[d] = pack2(xr, xr);
            }
            ull f[8];
            #pragma unroll
            for (int j = 0; j < 8; j++) f[j] = pack2(0.f, 0.f);
            #pragma unroll
            for (int d = 0; d < 8; d++) {
                const ulonglong2* wr = (const ulonglong2*)(wc + d * 16);
                #pragma unroll
                for (int k = 0; k < 4; k++) {
                    ulonglong2 wk = wr[k];
                    f[2 * k]     = ffma2(xrp[d], wk.x, f[2 * k]);
                    f[2 * k + 1] = ffma2(xrp[d], wk.y, f[2 * k + 1]);
                }
            }
            #pragma unroll
            for (int j = 0; j < 8; j++) h[j] = fmul2(h[j], f[j]);
        }

        // ---- epilogue: alpha from final denominators (reconstruct folded in) ----
        float A = 0.f;
        #pragma unroll
        for (int d = 0; d < 8; d++) {
            const ulonglong2* wr = (const ulonglong2*)(wc + d * 16);
            ull p = pack2(0.f, 0.f);
            #pragma unroll
            for (int k = 0; k < 4; k++) {
                ulonglong2 wk = wr[k];
                p = ffma2(h[2 * k],     wk.x, p);
                p = ffma2(h[2 * k + 1], wk.y, p);
            }
            float pa, pb; unpack2(p, pa, pb);
            A += xn[d] * wsum_sm[c * 8 + d] * (pa + pb);
        }
        ull s2 = fadd2(fadd2(h[0], h[1]), fadd2(h[2], h[3]));
        ull s3 = fadd2(fadd2(h[4], h[5]), fadd2(h[6], h[7]));
        s2 = fadd2(s2, s3);
        float sa, sb; unpack2(s2, sa, sb);
        float Sh  = sa + sb;
        float rSh = frcp(Sh);
        float ar  = A * rSh;                 // alpha (pre-normalization over c)
        alpha_sm[c * BATCH + lane] = ar;
        __syncthreads();
        float S = 0.f;
        #pragma unroll
        for (int cc = 0; cc < OC; cc++) S += alpha_sm[cc * BATCH + lane];
        float coeff = ar * frcp(S) * rSh;    // alpha_norm / Σh  (h → hn folded in)
        ull cp = pack2(coeff, coeff);
        #pragma unroll
        for (int j = 0; j < 8; j++) acc[j] = ffma2(cp, h[j], acc[j]);
        __syncthreads();   // protect smem before next i's staging
    }

    // ---- 144 partial sums per output element via REDG ----
    float* ob = out + lane * (OC * OD) + c * OD;
    #pragma unroll
    for (int j = 0; j < 8; j++) {
        float a_, b_; unpack2(acc[j], a_, b_);
        atomicAdd(ob + 2 * j,     a_);
        atomicAdd(ob + 2 * j + 1, b_);
    }
}

extern "C" void kernel_launch(void* const* d_in, const int* in_sizes, int n_in,
                              void* d_out, int out_size)
{
    const float* x = (const float*)d_in[0];
    const float* w = (const float*)d_in[1];
    // defensive: identify tensors by size (x = 294912, weights = 1474560)
    if (n_in >= 2 && in_sizes[0] == IC * OC * ID * OD && in_sizes[1] == BATCH * IC * ID) {
        x = (const float*)d_in[1];
        w = (const float*)d_in[0];
    }
    float* out = (float*)d_out;

    caps_zero_kernel<<<(BATCH * OC * OD + 255) / 256, 256>>>(out);
    caps_kernel<<<NBLK, THREADS>>>(x, w, out);
}